// round 1
// baseline (speedup 1.0000x reference)
#include <cuda_runtime.h>
#include <cuda_bf16.h>

#define N_NODES 50000
#define N_EDGES 400000
#define N_GRAPHS 64

// Scratch (device globals; no allocation allowed)
__device__ float g_buf1[N_NODES * 32];   // conv1 accumulator -> h1 (in-place relu)
__device__ float g_buf2[N_NODES * 16];   // conv2 accumulator
__device__ float g_pool[N_GRAPHS * 16];  // pooled graph features

// ---------------------------------------------------------------------------
// K1: agg1[n,o] = c1_bias[o] + sum_i x[n,i] * c1_root[i,o]   (o in [0,32))
// ---------------------------------------------------------------------------
__global__ void node_init1(const float* __restrict__ x,
                           const float* __restrict__ root,
                           const float* __restrict__ bias) {
    int t = blockIdx.x * blockDim.x + threadIdx.x;
    if (t >= N_NODES * 32) return;
    int n = t >> 5, o = t & 31;
    const float* xr = x + n * 16;
    float acc = bias[o];
#pragma unroll
    for (int i = 0; i < 16; i++) acc = fmaf(xr[i], root[i * 32 + o], acc);
    g_buf1[t] = acc;
}

// ---------------------------------------------------------------------------
// K2: conv1 edge kernel. Warp = 4 edges, lane = output channel o (32).
// msg[e,o] = sum_i x[src,i] * ( b2[i*32+o] + sum_k h[e,k]*w2[k, i*32+o] )
// atomicAdd into g_buf1[dst*32+o].
// ---------------------------------------------------------------------------
__global__ __launch_bounds__(256, 2) void edge1(
    const float* __restrict__ x, const int* __restrict__ ei,
    const float* __restrict__ ea,
    const float* __restrict__ w1, const float* __restrict__ b1,
    const float* __restrict__ w2, const float* __restrict__ b2) {
    extern __shared__ float sm[];
    float* s_w2 = sm;              // 32*512 = 16384
    float* s_w1 = s_w2 + 16384;    // 256
    float* s_b1 = s_w1 + 256;      // 32
    float* s_b2 = s_b1 + 32;       // 512
    float* s_h  = s_b2 + 512;      // 8 warps * 4 edges * 32

    int tid = threadIdx.x;
    for (int i = tid; i < 16384; i += 256) s_w2[i] = w2[i];
    for (int i = tid; i < 256;   i += 256) s_w1[i] = w1[i];
    if (tid < 32) s_b1[tid] = b1[tid];
    for (int i = tid; i < 512;   i += 256) s_b2[i] = b2[i];
    __syncthreads();

    int warp = tid >> 5, lane = tid & 31;
    long e0 = ((long)blockIdx.x * 8 + warp) * 4;
    float* sh = s_h + warp * 4 * 32;

    // edge MLP layer 1: h[e, lane] = relu(b1 + ea[e] @ w1[:,lane])
#pragma unroll
    for (int e = 0; e < 4; e++) {
        long ge = e0 + e;
        float acc = s_b1[lane];
        if (ge < N_EDGES) {
            const float* ear = ea + ge * 8;
#pragma unroll
            for (int j = 0; j < 8; j++) acc = fmaf(ear[j], s_w1[j * 32 + lane], acc);
        }
        sh[e * 32 + lane] = fmaxf(acc, 0.f);
    }
    __syncwarp();

    // main GEMM: acc[e][i] = sum_k h[e,k] * w2[k, i*32 + lane]
    float a[4][16];
#pragma unroll
    for (int e = 0; e < 4; e++)
#pragma unroll
        for (int i = 0; i < 16; i++) a[e][i] = 0.f;

#pragma unroll 4
    for (int k = 0; k < 32; k++) {
        float h0 = sh[0 * 32 + k];
        float h1 = sh[1 * 32 + k];
        float h2 = sh[2 * 32 + k];
        float h3 = sh[3 * 32 + k];
        const float* wr = s_w2 + k * 512 + lane;
#pragma unroll
        for (int i = 0; i < 16; i++) {
            float w = wr[i * 32];
            a[0][i] = fmaf(h0, w, a[0][i]);
            a[1][i] = fmaf(h1, w, a[1][i]);
            a[2][i] = fmaf(h2, w, a[2][i]);
            a[3][i] = fmaf(h3, w, a[3][i]);
        }
    }

    // epilogue: contract with x[src], scatter-add to dst
#pragma unroll
    for (int e = 0; e < 4; e++) {
        long ge = e0 + e;
        if (ge < N_EDGES) {
            int src = ei[ge];
            int dst = ei[N_EDGES + ge];
            const float* xs = x + src * 16;
            float m = 0.f;
#pragma unroll
            for (int i = 0; i < 16; i++)
                m = fmaf(xs[i], a[e][i] + s_b2[i * 32 + lane], m);
            atomicAdd(&g_buf1[dst * 32 + lane], m);
        }
    }
}

// ---------------------------------------------------------------------------
// K3: in-place relu of g_buf1 -> h1
// ---------------------------------------------------------------------------
__global__ void relu1(void) {
    int t = blockIdx.x * blockDim.x + threadIdx.x;
    if (t < N_NODES * 32) g_buf1[t] = fmaxf(g_buf1[t], 0.f);
}

// ---------------------------------------------------------------------------
// K4: agg2[n,o] = c2_bias[o] + sum_i h1[n,i] * c2_root[i,o]   (o in [0,16))
// ---------------------------------------------------------------------------
__global__ void node_init2(const float* __restrict__ root,
                           const float* __restrict__ bias) {
    int t = blockIdx.x * blockDim.x + threadIdx.x;
    if (t >= N_NODES * 16) return;
    int n = t >> 4, o = t & 15;
    const float* xr = g_buf1 + n * 32;
    float acc = bias[o];
#pragma unroll
    for (int i = 0; i < 32; i++) acc = fmaf(xr[i], root[i * 16 + o], acc);
    g_buf2[t] = acc;
}

// ---------------------------------------------------------------------------
// K5: conv2 edge kernel. Warp = 4 edges split over half-warps.
// lane = sub*16 + o; sub handles edges {sub*2, sub*2+1}; o = output (16).
// ---------------------------------------------------------------------------
__global__ __launch_bounds__(256, 2) void edge2(
    const int* __restrict__ ei, const float* __restrict__ ea,
    const float* __restrict__ w1, const float* __restrict__ b1,
    const float* __restrict__ w2, const float* __restrict__ b2) {
    extern __shared__ float sm[];
    float* s_w2 = sm;              // 32*512 = 16384
    float* s_w1 = s_w2 + 16384;    // 256
    float* s_b1 = s_w1 + 256;      // 32
    float* s_b2 = s_b1 + 32;       // 512
    float* s_h  = s_b2 + 512;      // 8 warps * 4 edges * 33 (padded)

    int tid = threadIdx.x;
    for (int i = tid; i < 16384; i += 256) s_w2[i] = w2[i];
    for (int i = tid; i < 256;   i += 256) s_w1[i] = w1[i];
    if (tid < 32) s_b1[tid] = b1[tid];
    for (int i = tid; i < 512;   i += 256) s_b2[i] = b2[i];
    __syncthreads();

    int warp = tid >> 5, lane = tid & 31;
    int sub = lane >> 4, o = lane & 15;
    long e0 = ((long)blockIdx.x * 8 + warp) * 4;
    float* sh = s_h + warp * 4 * 33;

    // edge MLP layer 1 (k = lane, all 32 lanes)
#pragma unroll
    for (int e = 0; e < 4; e++) {
        long ge = e0 + e;
        float acc = s_b1[lane];
        if (ge < N_EDGES) {
            const float* ear = ea + ge * 8;
#pragma unroll
            for (int j = 0; j < 8; j++) acc = fmaf(ear[j], s_w1[j * 32 + lane], acc);
        }
        sh[e * 33 + lane] = fmaxf(acc, 0.f);
    }
    __syncwarp();

    float a[2][32];
#pragma unroll
    for (int t2 = 0; t2 < 2; t2++)
#pragma unroll
        for (int i = 0; i < 32; i++) a[t2][i] = 0.f;

#pragma unroll 2
    for (int k = 0; k < 32; k++) {
        float hA = sh[(sub * 2 + 0) * 33 + k];
        float hB = sh[(sub * 2 + 1) * 33 + k];
        const float* wr = s_w2 + k * 512 + o;
#pragma unroll
        for (int i = 0; i < 32; i++) {
            float w = wr[i * 16];
            a[0][i] = fmaf(hA, w, a[0][i]);
            a[1][i] = fmaf(hB, w, a[1][i]);
        }
    }

#pragma unroll
    for (int t2 = 0; t2 < 2; t2++) {
        long ge = e0 + sub * 2 + t2;
        if (ge < N_EDGES) {
            int src = ei[ge];
            int dst = ei[N_EDGES + ge];
            const float* xs = g_buf1 + src * 32;
            float m = 0.f;
#pragma unroll
            for (int i = 0; i < 32; i++)
                m = fmaf(xs[i], a[t2][i] + s_b2[i * 16 + o], m);
            atomicAdd(&g_buf2[dst * 16 + o], m);
        }
    }
}

// ---------------------------------------------------------------------------
// K6a: zero pooled buffer
// ---------------------------------------------------------------------------
__global__ void zero_pool(void) {
    int t = blockIdx.x * blockDim.x + threadIdx.x;
    if (t < N_GRAPHS * 16) g_pool[t] = 0.f;
}

// ---------------------------------------------------------------------------
// K6: relu(agg2) + global_add_pool via per-block shared accumulation
// ---------------------------------------------------------------------------
__global__ void pool_kernel(const int* __restrict__ batch) {
    __shared__ float sg[N_GRAPHS * 16];
    int tid = threadIdx.x;
    for (int i = tid; i < N_GRAPHS * 16; i += blockDim.x) sg[i] = 0.f;
    __syncthreads();
    int t = blockIdx.x * blockDim.x + tid;
    int stride = gridDim.x * blockDim.x;
    for (int n = t; n < N_NODES; n += stride) {
        int b = batch[n];
        const float* r = g_buf2 + n * 16;
#pragma unroll
        for (int f = 0; f < 16; f++)
            atomicAdd(&sg[b * 16 + f], fmaxf(r[f], 0.f));
    }
    __syncthreads();
    for (int i = tid; i < N_GRAPHS * 16; i += blockDim.x)
        if (sg[i] != 0.f) atomicAdd(&g_pool[i], sg[i]);
}

// ---------------------------------------------------------------------------
// K7: head — per-graph MLP
// ---------------------------------------------------------------------------
__global__ void head_kernel(const float* __restrict__ fc1_w,
                            const float* __restrict__ fc1_b,
                            const float* __restrict__ out_w,
                            const float* __restrict__ out_b,
                            float* __restrict__ out) {
    int t = threadIdx.x;
    if (t >= N_GRAPHS) return;
    const float* gr = g_pool + t * 16;
    float r = out_b[0];
#pragma unroll
    for (int o = 0; o < 32; o++) {
        float acc = fc1_b[o];
#pragma unroll
        for (int i = 0; i < 16; i++) acc = fmaf(gr[i], fc1_w[i * 32 + o], acc);
        r = fmaf(fmaxf(acc, 0.f), out_w[o], r);
    }
    out[t] = r;
}

// ---------------------------------------------------------------------------
extern "C" void kernel_launch(void* const* d_in, const int* in_sizes, int n_in,
                              void* d_out, int out_size) {
    const float* x        = (const float*)d_in[0];
    const int*   ei       = (const int*)  d_in[1];
    const float* ea       = (const float*)d_in[2];
    const int*   batch    = (const int*)  d_in[3];
    const float* c1_w1    = (const float*)d_in[4];
    const float* c1_b1    = (const float*)d_in[5];
    const float* c1_w2    = (const float*)d_in[6];
    const float* c1_b2    = (const float*)d_in[7];
    const float* c1_root  = (const float*)d_in[8];
    const float* c1_bias  = (const float*)d_in[9];
    const float* c2_w1    = (const float*)d_in[10];
    const float* c2_b1    = (const float*)d_in[11];
    const float* c2_w2    = (const float*)d_in[12];
    const float* c2_b2    = (const float*)d_in[13];
    const float* c2_root  = (const float*)d_in[14];
    const float* c2_bias  = (const float*)d_in[15];
    const float* fc1_w    = (const float*)d_in[16];
    const float* fc1_b    = (const float*)d_in[17];
    const float* out_w    = (const float*)d_in[18];
    const float* out_b    = (const float*)d_in[19];
    float* out = (float*)d_out;

    const int smem_edge = (16384 + 256 + 32 + 512 + 8 * 4 * 33) * 4;
    cudaFuncSetAttribute(edge1, cudaFuncAttributeMaxDynamicSharedMemorySize, smem_edge);
    cudaFuncSetAttribute(edge2, cudaFuncAttributeMaxDynamicSharedMemorySize, smem_edge);

    // conv1
    node_init1<<<(N_NODES * 32 + 255) / 256, 256>>>(x, c1_root, c1_bias);
    edge1<<<(N_EDGES + 31) / 32, 256, smem_edge>>>(x, ei, ea, c1_w1, c1_b1, c1_w2, c1_b2);
    relu1<<<(N_NODES * 32 + 255) / 256, 256>>>();
    // conv2
    node_init2<<<(N_NODES * 16 + 255) / 256, 256>>>(c2_root, c2_bias);
    edge2<<<(N_EDGES + 31) / 32, 256, smem_edge>>>(ei, ea, c2_w1, c2_b1, c2_w2, c2_b2);
    // pool + head
    zero_pool<<<1, 1024>>>();
    pool_kernel<<<120, 256>>>(batch);
    head_kernel<<<1, 64>>>(fc1_w, fc1_b, out_w, out_b, out);
}

// round 2
// speedup vs baseline: 1.2747x; 1.2747x over previous
#include <cuda_runtime.h>
#include <cuda_bf16.h>

#define N_NODES 50000
#define N_EDGES 400000
#define N_GRAPHS 64
#define EDGE_GRID 592

typedef unsigned long long u64;

// Packed fp32x2 helpers (Blackwell FFMA2 path)
__device__ __forceinline__ u64 pack2(float a, float b) {
    u64 r; asm("mov.b64 %0,{%1,%2};" : "=l"(r) : "f"(a), "f"(b)); return r;
}
__device__ __forceinline__ u64 fma2(u64 a, u64 b, u64 c) {
    u64 d; asm("fma.rn.f32x2 %0,%1,%2,%3;" : "=l"(d) : "l"(a), "l"(b), "l"(c)); return d;
}
__device__ __forceinline__ float hadd2(u64 v) {
    float lo, hi; asm("mov.b64 {%0,%1},%2;" : "=f"(lo), "=f"(hi) : "l"(v)); return lo + hi;
}

// Scratch (device globals; no allocation allowed)
__device__ float g_buf1[N_NODES * 32];   // conv1 accumulator -> h1 (in-place relu)
__device__ float g_buf2[N_NODES * 16];   // conv2 accumulator
__device__ float g_pool[N_GRAPHS * 16];  // pooled graph features

// ---------------------------------------------------------------------------
// K1: agg1[n,o] = c1_bias[o] + sum_i x[n,i] * c1_root[i,o]
// ---------------------------------------------------------------------------
__global__ void node_init1(const float* __restrict__ x,
                           const float* __restrict__ root,
                           const float* __restrict__ bias) {
    int t = blockIdx.x * blockDim.x + threadIdx.x;
    if (t >= N_NODES * 32) return;
    int n = t >> 5, o = t & 31;
    const float* xr = x + n * 16;
    float acc = bias[o];
#pragma unroll
    for (int i = 0; i < 16; i++) acc = fmaf(xr[i], root[i * 32 + o], acc);
    g_buf1[t] = acc;
}

// ---------------------------------------------------------------------------
// K2: conv1 edge kernel. Warp = 4 edges, lane = output channel o (32).
// Packed over i-pairs: acc[e][ip] = (We[e,2ip,o], We[e,2ip+1,o]).
// b2 folded in as k=32 row with h=1.
// ---------------------------------------------------------------------------
__global__ __launch_bounds__(256, 2) void edge1(
    const float* __restrict__ x, const int* __restrict__ ei,
    const float* __restrict__ ea,
    const float* __restrict__ w1, const float* __restrict__ b1,
    const float* __restrict__ w2, const float* __restrict__ b2) {
    extern __shared__ u64 sm64[];
    u64* s_w2p = sm64;                         // 33*8*32 = 8448 u64
    u64* s_h   = sm64 + 8448;                  // 8 warps * 132 = 1056 u64
    float* s_w1 = (float*)(sm64 + 9504);       // 256
    float* s_b1 = s_w1 + 256;                  // 32

    int tid = threadIdx.x;
    // s_w2p[(k*8+ip)*32+o] = (w2[k, (2ip)*32+o], w2[k, (2ip+1)*32+o]); k=32 -> b2
    for (int idx = tid; idx < 8448; idx += 256) {
        int k = idx >> 8;
        int r = idx & 255;
        int ip = r >> 5, o = r & 31;
        float lo, hi;
        if (k < 32) { lo = w2[k * 512 + ip * 64 + o]; hi = w2[k * 512 + ip * 64 + 32 + o]; }
        else        { lo = b2[ip * 64 + o];           hi = b2[ip * 64 + 32 + o]; }
        s_w2p[idx] = pack2(lo, hi);
    }
    s_w1[tid] = w1[tid];
    if (tid < 32) s_b1[tid] = b1[tid];
    __syncthreads();

    int warp = tid >> 5, lane = tid & 31;
    u64* sh = s_h + warp * 132;

    for (long g = (long)blockIdx.x * 8 + warp; g < N_EDGES / 4; g += (long)EDGE_GRID * 8) {
        long e0 = g * 4;
        // edge MLP layer 1: h[e, lane] = relu(b1 + ea[e] @ w1[:,lane]); store (h,h)
#pragma unroll
        for (int e = 0; e < 4; e++) {
            const float4* ear = (const float4*)(ea + (e0 + e) * 8);
            float4 a0 = __ldg(ear), a1 = __ldg(ear + 1);
            float acc = s_b1[lane];
            acc = fmaf(a0.x, s_w1[0 * 32 + lane], acc);
            acc = fmaf(a0.y, s_w1[1 * 32 + lane], acc);
            acc = fmaf(a0.z, s_w1[2 * 32 + lane], acc);
            acc = fmaf(a0.w, s_w1[3 * 32 + lane], acc);
            acc = fmaf(a1.x, s_w1[4 * 32 + lane], acc);
            acc = fmaf(a1.y, s_w1[5 * 32 + lane], acc);
            acc = fmaf(a1.z, s_w1[6 * 32 + lane], acc);
            acc = fmaf(a1.w, s_w1[7 * 32 + lane], acc);
            acc = fmaxf(acc, 0.f);
            sh[e * 33 + lane] = pack2(acc, acc);
        }
        if (lane < 4) sh[lane * 33 + 32] = pack2(1.f, 1.f);
        __syncwarp();

        u64 acc[4][8];
#pragma unroll
        for (int e = 0; e < 4; e++)
#pragma unroll
            for (int ip = 0; ip < 8; ip++) acc[e][ip] = 0ull;

#pragma unroll 3
        for (int k = 0; k < 33; k++) {
            u64 h0 = sh[0 * 33 + k];
            u64 h1 = sh[1 * 33 + k];
            u64 h2 = sh[2 * 33 + k];
            u64 h3 = sh[3 * 33 + k];
            const u64* wr = s_w2p + k * 256 + lane;
#pragma unroll
            for (int ip = 0; ip < 8; ip++) {
                u64 w = wr[ip * 32];
                acc[0][ip] = fma2(h0, w, acc[0][ip]);
                acc[1][ip] = fma2(h1, w, acc[1][ip]);
                acc[2][ip] = fma2(h2, w, acc[2][ip]);
                acc[3][ip] = fma2(h3, w, acc[3][ip]);
            }
        }
        __syncwarp();

        // epilogue: m[e,o] = sum_ip dot(x2[src,ip], acc[e][ip]); scatter-add
#pragma unroll
        for (int e = 0; e < 4; e++) {
            long ge = e0 + e;
            int src = __ldg(ei + ge);
            int dst = __ldg(ei + N_EDGES + ge);
            const u64* xs = (const u64*)(x + (long)src * 16);
            u64 s = 0ull;
#pragma unroll
            for (int ip = 0; ip < 8; ip++) s = fma2(__ldg(xs + ip), acc[e][ip], s);
            atomicAdd(&g_buf1[(long)dst * 32 + lane], hadd2(s));
        }
    }
}

// ---------------------------------------------------------------------------
// K3: in-place relu of g_buf1 -> h1
// ---------------------------------------------------------------------------
__global__ void relu1(void) {
    int t = blockIdx.x * blockDim.x + threadIdx.x;
    if (t < N_NODES * 32) g_buf1[t] = fmaxf(g_buf1[t], 0.f);
}

// ---------------------------------------------------------------------------
// K4: agg2[n,o] = c2_bias[o] + sum_i h1[n,i] * c2_root[i,o]
// ---------------------------------------------------------------------------
__global__ void node_init2(const float* __restrict__ root,
                           const float* __restrict__ bias) {
    int t = blockIdx.x * blockDim.x + threadIdx.x;
    if (t >= N_NODES * 16) return;
    int n = t >> 4, o = t & 15;
    const float* xr = g_buf1 + n * 32;
    float acc = bias[o];
#pragma unroll
    for (int i = 0; i < 32; i++) acc = fmaf(xr[i], root[i * 16 + o], acc);
    g_buf2[t] = acc;
}

// ---------------------------------------------------------------------------
// K5: conv2 edge kernel. Warp = 4 edges, half-warp sub owns edges {2sub,2sub+1}.
// lane = sub*16 + o. Packed over i-pairs (32 i -> 16 pairs).
// ---------------------------------------------------------------------------
__global__ __launch_bounds__(256, 2) void edge2(
    const int* __restrict__ ei, const float* __restrict__ ea,
    const float* __restrict__ w1, const float* __restrict__ b1,
    const float* __restrict__ w2, const float* __restrict__ b2) {
    extern __shared__ u64 sm64[];
    u64* s_w2p = sm64;                         // 33*16*16 = 8448 u64
    u64* s_h   = sm64 + 8448;                  // 1056 u64
    float* s_w1 = (float*)(sm64 + 9504);       // 256
    float* s_b1 = s_w1 + 256;                  // 32

    int tid = threadIdx.x;
    // s_w2p[(k*16+ip)*16+o] = (w2[k, (2ip)*16+o], w2[k, (2ip+1)*16+o]); k=32 -> b2
    for (int idx = tid; idx < 8448; idx += 256) {
        int k = idx >> 8;
        int r = idx & 255;
        int ip = r >> 4, o = r & 15;
        float lo, hi;
        if (k < 32) { lo = w2[k * 512 + ip * 32 + o]; hi = w2[k * 512 + ip * 32 + 16 + o]; }
        else        { lo = b2[ip * 32 + o];           hi = b2[ip * 32 + 16 + o]; }
        s_w2p[idx] = pack2(lo, hi);
    }
    s_w1[tid] = w1[tid];
    if (tid < 32) s_b1[tid] = b1[tid];
    __syncthreads();

    int warp = tid >> 5, lane = tid & 31;
    int sub = lane >> 4, o = lane & 15;
    u64* sh = s_h + warp * 132;
    int eA = 2 * sub, eB = 2 * sub + 1;

    for (long g = (long)blockIdx.x * 8 + warp; g < N_EDGES / 4; g += (long)EDGE_GRID * 8) {
        long e0 = g * 4;
#pragma unroll
        for (int e = 0; e < 4; e++) {
            const float4* ear = (const float4*)(ea + (e0 + e) * 8);
            float4 a0 = __ldg(ear), a1 = __ldg(ear + 1);
            float acc = s_b1[lane];
            acc = fmaf(a0.x, s_w1[0 * 32 + lane], acc);
            acc = fmaf(a0.y, s_w1[1 * 32 + lane], acc);
            acc = fmaf(a0.z, s_w1[2 * 32 + lane], acc);
            acc = fmaf(a0.w, s_w1[3 * 32 + lane], acc);
            acc = fmaf(a1.x, s_w1[4 * 32 + lane], acc);
            acc = fmaf(a1.y, s_w1[5 * 32 + lane], acc);
            acc = fmaf(a1.z, s_w1[6 * 32 + lane], acc);
            acc = fmaf(a1.w, s_w1[7 * 32 + lane], acc);
            acc = fmaxf(acc, 0.f);
            sh[e * 33 + lane] = pack2(acc, acc);
        }
        if (lane < 4) sh[lane * 33 + 32] = pack2(1.f, 1.f);
        __syncwarp();

        u64 acc[2][16];
#pragma unroll
        for (int t2 = 0; t2 < 2; t2++)
#pragma unroll
            for (int ip = 0; ip < 16; ip++) acc[t2][ip] = 0ull;

#pragma unroll 3
        for (int k = 0; k < 33; k++) {
            u64 hA = sh[eA * 33 + k];
            u64 hB = sh[eB * 33 + k];
            const u64* wr = s_w2p + k * 256 + o;
#pragma unroll
            for (int ip = 0; ip < 16; ip++) {
                u64 w = wr[ip * 16];
                acc[0][ip] = fma2(hA, w, acc[0][ip]);
                acc[1][ip] = fma2(hB, w, acc[1][ip]);
            }
        }
        __syncwarp();

#pragma unroll
        for (int t2 = 0; t2 < 2; t2++) {
            long ge = e0 + eA + t2;
            int src = __ldg(ei + ge);
            int dst = __ldg(ei + N_EDGES + ge);
            const u64* xs = (const u64*)(g_buf1 + (long)src * 32);
            u64 s = 0ull;
#pragma unroll
            for (int ip = 0; ip < 16; ip++) s = fma2(__ldg(xs + ip), acc[t2][ip], s);
            atomicAdd(&g_buf2[(long)dst * 16 + o], hadd2(s));
        }
    }
}

// ---------------------------------------------------------------------------
// K6a: zero pooled buffer
// ---------------------------------------------------------------------------
__global__ void zero_pool(void) {
    int t = blockIdx.x * blockDim.x + threadIdx.x;
    if (t < N_GRAPHS * 16) g_pool[t] = 0.f;
}

// ---------------------------------------------------------------------------
// K6: relu(agg2) + global_add_pool via per-block shared accumulation
// ---------------------------------------------------------------------------
__global__ void pool_kernel(const int* __restrict__ batch) {
    __shared__ float sg[N_GRAPHS * 16];
    int tid = threadIdx.x;
    for (int i = tid; i < N_GRAPHS * 16; i += blockDim.x) sg[i] = 0.f;
    __syncthreads();
    int t = blockIdx.x * blockDim.x + tid;
    int stride = gridDim.x * blockDim.x;
    for (int n = t; n < N_NODES; n += stride) {
        int b = batch[n];
        const float* r = g_buf2 + n * 16;
#pragma unroll
        for (int f = 0; f < 16; f++)
            atomicAdd(&sg[b * 16 + f], fmaxf(r[f], 0.f));
    }
    __syncthreads();
    for (int i = tid; i < N_GRAPHS * 16; i += blockDim.x)
        if (sg[i] != 0.f) atomicAdd(&g_pool[i], sg[i]);
}

// ---------------------------------------------------------------------------
// K7: head — per-graph MLP
// ---------------------------------------------------------------------------
__global__ void head_kernel(const float* __restrict__ fc1_w,
                            const float* __restrict__ fc1_b,
                            const float* __restrict__ out_w,
                            const float* __restrict__ out_b,
                            float* __restrict__ out) {
    int t = threadIdx.x;
    if (t >= N_GRAPHS) return;
    const float* gr = g_pool + t * 16;
    float r = out_b[0];
#pragma unroll
    for (int o = 0; o < 32; o++) {
        float acc = fc1_b[o];
#pragma unroll
        for (int i = 0; i < 16; i++) acc = fmaf(gr[i], fc1_w[i * 32 + o], acc);
        r = fmaf(fmaxf(acc, 0.f), out_w[o], r);
    }
    out[t] = r;
}

// ---------------------------------------------------------------------------
extern "C" void kernel_launch(void* const* d_in, const int* in_sizes, int n_in,
                              void* d_out, int out_size) {
    const float* x        = (const float*)d_in[0];
    const int*   ei       = (const int*)  d_in[1];
    const float* ea       = (const float*)d_in[2];
    const int*   batch    = (const int*)  d_in[3];
    const float* c1_w1    = (const float*)d_in[4];
    const float* c1_b1    = (const float*)d_in[5];
    const float* c1_w2    = (const float*)d_in[6];
    const float* c1_b2    = (const float*)d_in[7];
    const float* c1_root  = (const float*)d_in[8];
    const float* c1_bias  = (const float*)d_in[9];
    const float* c2_w1    = (const float*)d_in[10];
    const float* c2_b1    = (const float*)d_in[11];
    const float* c2_w2    = (const float*)d_in[12];
    const float* c2_b2    = (const float*)d_in[13];
    const float* c2_root  = (const float*)d_in[14];
    const float* c2_bias  = (const float*)d_in[15];
    const float* fc1_w    = (const float*)d_in[16];
    const float* fc1_b    = (const float*)d_in[17];
    const float* out_w    = (const float*)d_in[18];
    const float* out_b    = (const float*)d_in[19];
    float* out = (float*)d_out;

    // smem: 9504 u64 + (256+32) floats = 76032 + 1152 = 77184 bytes
    const int smem_edge = 9504 * 8 + 288 * 4;
    cudaFuncSetAttribute(edge1, cudaFuncAttributeMaxDynamicSharedMemorySize, smem_edge);
    cudaFuncSetAttribute(edge2, cudaFuncAttributeMaxDynamicSharedMemorySize, smem_edge);

    // conv1
    node_init1<<<(N_NODES * 32 + 255) / 256, 256>>>(x, c1_root, c1_bias);
    edge1<<<EDGE_GRID, 256, smem_edge>>>(x, ei, ea, c1_w1, c1_b1, c1_w2, c1_b2);
    relu1<<<(N_NODES * 32 + 255) / 256, 256>>>();
    // conv2
    node_init2<<<(N_NODES * 16 + 255) / 256, 256>>>(c2_root, c2_bias);
    edge2<<<EDGE_GRID, 256, smem_edge>>>(ei, ea, c2_w1, c2_b1, c2_w2, c2_b2);
    // pool + head
    zero_pool<<<1, 1024>>>();
    pool_kernel<<<120, 256>>>(batch);
    head_kernel<<<1, 64>>>(fc1_w, fc1_b, out_w, out_b, out);
}

// round 3
// speedup vs baseline: 1.4824x; 1.1629x over previous
#include <cuda_runtime.h>
#include <cuda_bf16.h>

#define N_NODES 50000
#define N_EDGES 400000
#define N_GRAPHS 64
#define EDGE_GRID 592

typedef unsigned long long u64;

// Packed fp32x2 helpers (Blackwell FFMA2 path)
__device__ __forceinline__ u64 pack2(float a, float b) {
    u64 r; asm("mov.b64 %0,{%1,%2};" : "=l"(r) : "f"(a), "f"(b)); return r;
}
__device__ __forceinline__ u64 fma2(u64 a, u64 b, u64 c) {
    u64 d; asm("fma.rn.f32x2 %0,%1,%2,%3;" : "=l"(d) : "l"(a), "l"(b), "l"(c)); return d;
}
__device__ __forceinline__ float hadd2(u64 v) {
    float lo, hi; asm("mov.b64 {%0,%1},%2;" : "=f"(lo), "=f"(hi) : "l"(v)); return lo + hi;
}

// Scratch (device globals; no allocation allowed)
__device__ float g_buf1[N_NODES * 32];   // conv1 accumulator -> h1 (in-place relu)
__device__ float g_buf2[N_NODES * 16];   // conv2 accumulator
__device__ float g_pool[N_GRAPHS * 16];  // pooled graph features

// ---------------------------------------------------------------------------
// K1: agg1[n,o] = c1_bias[o] + sum_i x[n,i] * c1_root[i,o]
// ---------------------------------------------------------------------------
__global__ void node_init1(const float* __restrict__ x,
                           const float* __restrict__ root,
                           const float* __restrict__ bias) {
    int t = blockIdx.x * blockDim.x + threadIdx.x;
    if (t >= N_NODES * 32) return;
    int n = t >> 5, o = t & 31;
    const float* xr = x + n * 16;
    float acc = bias[o];
#pragma unroll
    for (int i = 0; i < 16; i++) acc = fmaf(xr[i], root[i * 32 + o], acc);
    g_buf1[t] = acc;
}

// ---------------------------------------------------------------------------
// K2: conv1 edge kernel. Warp = 8 edges, lane = output channel o (32).
// acc[e][ip] = packed (We[e,2ip,o], We[e,2ip+1,o]); b2 folded as k=32, h=1.
// ---------------------------------------------------------------------------
__global__ __launch_bounds__(256, 1) void edge1(
    const float* __restrict__ x, const int* __restrict__ ei,
    const float* __restrict__ ea,
    const float* __restrict__ w1, const float* __restrict__ b1,
    const float* __restrict__ w2, const float* __restrict__ b2) {
    extern __shared__ u64 sm64[];
    u64* s_w2p = sm64;                         // 33*8*32 = 8448 u64
    u64* s_h   = sm64 + 8448;                  // 8 warps * 264 = 2112 u64
    float* s_w1 = (float*)(sm64 + 10560);      // 256
    float* s_b1 = s_w1 + 256;                  // 32

    int tid = threadIdx.x;
    // s_w2p[(k*8+ip)*32+o] = (w2[k,(2ip)*32+o], w2[k,(2ip+1)*32+o]); k=32 -> b2
    for (int idx = tid; idx < 8448; idx += 256) {
        int k = idx >> 8;
        int r = idx & 255;
        int ip = r >> 5, o = r & 31;
        float lo, hi;
        if (k < 32) { lo = w2[k * 512 + ip * 64 + o]; hi = w2[k * 512 + ip * 64 + 32 + o]; }
        else        { lo = b2[ip * 64 + o];           hi = b2[ip * 64 + 32 + o]; }
        s_w2p[idx] = pack2(lo, hi);
    }
    s_w1[tid] = w1[tid];
    if (tid < 32) s_b1[tid] = b1[tid];
    __syncthreads();

    int warp = tid >> 5, lane = tid & 31;
    u64* sh = s_h + warp * 264;

    for (long g = (long)blockIdx.x * 8 + warp; g < N_EDGES / 8; g += (long)EDGE_GRID * 8) {
        long e0 = g * 8;
        // prefetch edge endpoints (independent of mainloop)
        int srcs[8], dsts[8];
#pragma unroll
        for (int e = 0; e < 8; e++) {
            srcs[e] = __ldg(ei + e0 + e);
            dsts[e] = __ldg(ei + N_EDGES + e0 + e);
        }
        // edge MLP layer 1: h[e,lane] = relu(b1 + ea[e] @ w1[:,lane]); store (h,h)
#pragma unroll
        for (int e = 0; e < 8; e++) {
            const float4* ear = (const float4*)(ea + (e0 + e) * 8);
            float4 a0 = __ldg(ear), a1 = __ldg(ear + 1);
            float acc = s_b1[lane];
            acc = fmaf(a0.x, s_w1[0 * 32 + lane], acc);
            acc = fmaf(a0.y, s_w1[1 * 32 + lane], acc);
            acc = fmaf(a0.z, s_w1[2 * 32 + lane], acc);
            acc = fmaf(a0.w, s_w1[3 * 32 + lane], acc);
            acc = fmaf(a1.x, s_w1[4 * 32 + lane], acc);
            acc = fmaf(a1.y, s_w1[5 * 32 + lane], acc);
            acc = fmaf(a1.z, s_w1[6 * 32 + lane], acc);
            acc = fmaf(a1.w, s_w1[7 * 32 + lane], acc);
            acc = fmaxf(acc, 0.f);
            sh[e * 33 + lane] = pack2(acc, acc);
        }
        if (lane < 8) sh[lane * 33 + 32] = pack2(1.f, 1.f);
        __syncwarp();

        u64 acc[8][8];
#pragma unroll
        for (int e = 0; e < 8; e++)
#pragma unroll
            for (int ip = 0; ip < 8; ip++) acc[e][ip] = 0ull;

#pragma unroll 3
        for (int k = 0; k < 33; k++) {
            u64 h[8];
#pragma unroll
            for (int e = 0; e < 8; e++) h[e] = sh[e * 33 + k];
            const u64* wr = s_w2p + k * 256 + lane;
#pragma unroll
            for (int ip = 0; ip < 8; ip++) {
                u64 w = wr[ip * 32];
#pragma unroll
                for (int e = 0; e < 8; e++) acc[e][ip] = fma2(h[e], w, acc[e][ip]);
            }
        }
        __syncwarp();

        // epilogue: m[e,o] = sum_ip dot(x2[src,ip], acc[e][ip]); scatter-add
#pragma unroll
        for (int e = 0; e < 8; e++) {
            const u64* xs = (const u64*)(x + (long)srcs[e] * 16);
            u64 s = 0ull;
#pragma unroll
            for (int ip = 0; ip < 8; ip++) s = fma2(__ldg(xs + ip), acc[e][ip], s);
            atomicAdd(&g_buf1[(long)dsts[e] * 32 + lane], hadd2(s));
        }
    }
}

// ---------------------------------------------------------------------------
// K3: in-place relu of g_buf1 -> h1
// ---------------------------------------------------------------------------
__global__ void relu1(void) {
    int t = blockIdx.x * blockDim.x + threadIdx.x;
    if (t < N_NODES * 32) g_buf1[t] = fmaxf(g_buf1[t], 0.f);
}

// ---------------------------------------------------------------------------
// K4: agg2[n,o] = c2_bias[o] + sum_i h1[n,i] * c2_root[i,o]
// ---------------------------------------------------------------------------
__global__ void node_init2(const float* __restrict__ root,
                           const float* __restrict__ bias) {
    int t = blockIdx.x * blockDim.x + threadIdx.x;
    if (t >= N_NODES * 16) return;
    int n = t >> 4, o = t & 15;
    const float* xr = g_buf1 + n * 32;
    float acc = bias[o];
#pragma unroll
    for (int i = 0; i < 32; i++) acc = fmaf(xr[i], root[i * 16 + o], acc);
    g_buf2[t] = acc;
}

// ---------------------------------------------------------------------------
// K5: conv2 edge kernel. Warp = 8 edges; half-warp sub owns edges sub*4..+3.
// lane = sub*16 + o. Packed over i-pairs (32 i -> 16 pairs).
// ---------------------------------------------------------------------------
__global__ __launch_bounds__(256, 1) void edge2(
    const int* __restrict__ ei, const float* __restrict__ ea,
    const float* __restrict__ w1, const float* __restrict__ b1,
    const float* __restrict__ w2, const float* __restrict__ b2) {
    extern __shared__ u64 sm64[];
    u64* s_w2p = sm64;                         // 33*16*16 = 8448 u64
    u64* s_h   = sm64 + 8448;                  // 8 warps * 264 = 2112 u64
    float* s_w1 = (float*)(sm64 + 10560);      // 256
    float* s_b1 = s_w1 + 256;                  // 32

    int tid = threadIdx.x;
    // s_w2p[(k*16+ip)*16+o] = (w2[k,(2ip)*16+o], w2[k,(2ip+1)*16+o]); k=32 -> b2
    for (int idx = tid; idx < 8448; idx += 256) {
        int k = idx >> 8;
        int r = idx & 255;
        int ip = r >> 4, o = r & 15;
        float lo, hi;
        if (k < 32) { lo = w2[k * 512 + ip * 32 + o]; hi = w2[k * 512 + ip * 32 + 16 + o]; }
        else        { lo = b2[ip * 32 + o];           hi = b2[ip * 32 + 16 + o]; }
        s_w2p[idx] = pack2(lo, hi);
    }
    s_w1[tid] = w1[tid];
    if (tid < 32) s_b1[tid] = b1[tid];
    __syncthreads();

    int warp = tid >> 5, lane = tid & 31;
    int sub = lane >> 4, o = lane & 15;
    u64* sh = s_h + warp * 264;

    for (long g = (long)blockIdx.x * 8 + warp; g < N_EDGES / 8; g += (long)EDGE_GRID * 8) {
        long e0 = g * 8;
        int srcs[4], dsts[4];
#pragma unroll
        for (int t2 = 0; t2 < 4; t2++) {
            long ge = e0 + sub * 4 + t2;
            srcs[t2] = __ldg(ei + ge);
            dsts[t2] = __ldg(ei + N_EDGES + ge);
        }
#pragma unroll
        for (int e = 0; e < 8; e++) {
            const float4* ear = (const float4*)(ea + (e0 + e) * 8);
            float4 a0 = __ldg(ear), a1 = __ldg(ear + 1);
            float acc = s_b1[lane];
            acc = fmaf(a0.x, s_w1[0 * 32 + lane], acc);
            acc = fmaf(a0.y, s_w1[1 * 32 + lane], acc);
            acc = fmaf(a0.z, s_w1[2 * 32 + lane], acc);
            acc = fmaf(a0.w, s_w1[3 * 32 + lane], acc);
            acc = fmaf(a1.x, s_w1[4 * 32 + lane], acc);
            acc = fmaf(a1.y, s_w1[5 * 32 + lane], acc);
            acc = fmaf(a1.z, s_w1[6 * 32 + lane], acc);
            acc = fmaf(a1.w, s_w1[7 * 32 + lane], acc);
            acc = fmaxf(acc, 0.f);
            sh[e * 33 + lane] = pack2(acc, acc);
        }
        if (lane < 8) sh[lane * 33 + 32] = pack2(1.f, 1.f);
        __syncwarp();

        u64 acc[4][16];
#pragma unroll
        for (int t2 = 0; t2 < 4; t2++)
#pragma unroll
            for (int ip = 0; ip < 16; ip++) acc[t2][ip] = 0ull;

#pragma unroll 3
        for (int k = 0; k < 33; k++) {
            u64 h[4];
#pragma unroll
            for (int t2 = 0; t2 < 4; t2++) h[t2] = sh[(sub * 4 + t2) * 33 + k];
            const u64* wr = s_w2p + k * 256 + o;
#pragma unroll
            for (int ip = 0; ip < 16; ip++) {
                u64 w = wr[ip * 16];
#pragma unroll
                for (int t2 = 0; t2 < 4; t2++) acc[t2][ip] = fma2(h[t2], w, acc[t2][ip]);
            }
        }
        __syncwarp();

#pragma unroll
        for (int t2 = 0; t2 < 4; t2++) {
            const u64* xs = (const u64*)(g_buf1 + (long)srcs[t2] * 32);
            u64 s = 0ull;
#pragma unroll
            for (int ip = 0; ip < 16; ip++) s = fma2(__ldg(xs + ip), acc[t2][ip], s);
            atomicAdd(&g_buf2[(long)dsts[t2] * 16 + o], hadd2(s));
        }
    }
}

// ---------------------------------------------------------------------------
// K6a: zero pooled buffer
// ---------------------------------------------------------------------------
__global__ void zero_pool(void) {
    int t = blockIdx.x * blockDim.x + threadIdx.x;
    if (t < N_GRAPHS * 16) g_pool[t] = 0.f;
}

// ---------------------------------------------------------------------------
// K6: relu(agg2) + global_add_pool via per-block shared accumulation
// ---------------------------------------------------------------------------
__global__ void pool_kernel(const int* __restrict__ batch) {
    __shared__ float sg[N_GRAPHS * 16];
    int tid = threadIdx.x;
    for (int i = tid; i < N_GRAPHS * 16; i += blockDim.x) sg[i] = 0.f;
    __syncthreads();
    int t = blockIdx.x * blockDim.x + tid;
    int stride = gridDim.x * blockDim.x;
    for (int n = t; n < N_NODES; n += stride) {
        int b = batch[n];
        const float* r = g_buf2 + n * 16;
#pragma unroll
        for (int f = 0; f < 16; f++)
            atomicAdd(&sg[b * 16 + f], fmaxf(r[f], 0.f));
    }
    __syncthreads();
    for (int i = tid; i < N_GRAPHS * 16; i += blockDim.x)
        if (sg[i] != 0.f) atomicAdd(&g_pool[i], sg[i]);
}

// ---------------------------------------------------------------------------
// K7: head — per-graph MLP
// ---------------------------------------------------------------------------
__global__ void head_kernel(const float* __restrict__ fc1_w,
                            const float* __restrict__ fc1_b,
                            const float* __restrict__ out_w,
                            const float* __restrict__ out_b,
                            float* __restrict__ out) {
    int t = threadIdx.x;
    if (t >= N_GRAPHS) return;
    const float* gr = g_pool + t * 16;
    float r = out_b[0];
#pragma unroll
    for (int o = 0; o < 32; o++) {
        float acc = fc1_b[o];
#pragma unroll
        for (int i = 0; i < 16; i++) acc = fmaf(gr[i], fc1_w[i * 32 + o], acc);
        r = fmaf(fmaxf(acc, 0.f), out_w[o], r);
    }
    out[t] = r;
}

// ---------------------------------------------------------------------------
extern "C" void kernel_launch(void* const* d_in, const int* in_sizes, int n_in,
                              void* d_out, int out_size) {
    const float* x        = (const float*)d_in[0];
    const int*   ei       = (const int*)  d_in[1];
    const float* ea       = (const float*)d_in[2];
    const int*   batch    = (const int*)  d_in[3];
    const float* c1_w1    = (const float*)d_in[4];
    const float* c1_b1    = (const float*)d_in[5];
    const float* c1_w2    = (const float*)d_in[6];
    const float* c1_b2    = (const float*)d_in[7];
    const float* c1_root  = (const float*)d_in[8];
    const float* c1_bias  = (const float*)d_in[9];
    const float* c2_w1    = (const float*)d_in[10];
    const float* c2_b1    = (const float*)d_in[11];
    const float* c2_w2    = (const float*)d_in[12];
    const float* c2_b2    = (const float*)d_in[13];
    const float* c2_root  = (const float*)d_in[14];
    const float* c2_bias  = (const float*)d_in[15];
    const float* fc1_w    = (const float*)d_in[16];
    const float* fc1_b    = (const float*)d_in[17];
    const float* out_w    = (const float*)d_in[18];
    const float* out_b    = (const float*)d_in[19];
    float* out = (float*)d_out;

    // smem: 10560 u64 + (256+32) floats = 84480 + 1152 = 85632 bytes
    const int smem_edge = 10560 * 8 + 288 * 4;
    cudaFuncSetAttribute(edge1, cudaFuncAttributeMaxDynamicSharedMemorySize, smem_edge);
    cudaFuncSetAttribute(edge2, cudaFuncAttributeMaxDynamicSharedMemorySize, smem_edge);

    // conv1
    node_init1<<<(N_NODES * 32 + 255) / 256, 256>>>(x, c1_root, c1_bias);
    edge1<<<EDGE_GRID, 256, smem_edge>>>(x, ei, ea, c1_w1, c1_b1, c1_w2, c1_b2);
    relu1<<<(N_NODES * 32 + 255) / 256, 256>>>();
    // conv2
    node_init2<<<(N_NODES * 16 + 255) / 256, 256>>>(c2_root, c2_bias);
    edge2<<<EDGE_GRID, 256, smem_edge>>>(ei, ea, c2_w1, c2_b1, c2_w2, c2_b2);
    // pool + head
    zero_pool<<<1, 1024>>>();
    pool_kernel<<<120, 256>>>(batch);
    head_kernel<<<1, 64>>>(fc1_w, fc1_b, out_w, out_b, out);
}